// round 7
// baseline (speedup 1.0000x reference)
#include <cuda_runtime.h>
#include <cuda_fp16.h>
#include <cuda_bf16.h>

// ---------------------------------------------------------------------------
// TextGCN 2-layer GCN, CSR gather formulation, fp16 hidden storage.
//   dinv = rsqrt(1 + sum_{e:col=i} w_e)
//   hsraw = x @ W              (stored fp16)
//   x'    = relu(dinv_i * (dinv_i*hsraw_i + sum_in hsraw_r * (w*dinv_r)) + b)
// Edge weights pre-folded with dinv[row] at CSR placement.
// ---------------------------------------------------------------------------

#define N_NODES 100000
#define E_EDGES 3200000
#define HID 128
#define NCLS 16

#define SCAN_T 256
#define SCAN_V 4
#define SCAN_E (SCAN_T * SCAN_V)                       // 1024
#define SCAN_NB ((N_NODES + SCAN_E - 1) / SCAN_E)      // 98

// scratch (device globals: no allocation allowed)
__device__ int   g_is64;
__device__ int   g_deg [N_NODES];
__device__ int   g_off [N_NODES + 1];
__device__ int   g_cur [N_NODES];
__device__ int   g_bsum[SCAN_NB];
__device__ int   g_bpre[SCAN_NB];
__device__ __align__(16) int2   g_erec[E_EDGES];       // (row, bits(w*dinv[row]))
__device__ __align__(16) float  g_dinv[N_NODES];
__device__ __align__(16) __half g_hsh[(size_t)N_NODES * HID];   // hsraw fp16
__device__ __align__(16) float  g_acc[(size_t)N_NODES * HID];   // layer-1 out x
__device__ __align__(16) float  g_h2 [(size_t)N_NODES * NCLS];  // layer-2 hsraw

// ---------------------------------------------------------------------------
__global__ void k_detect(const int* __restrict__ ei32) {
    if (threadIdx.x == 0 && blockIdx.x == 0) {
        int nz = 0;
        #pragma unroll 1
        for (int i = 1; i < 2048; i += 2) nz |= (ei32[i] != 0);
        g_is64 = (nz == 0) ? 1 : 0;
    }
}

__global__ void k_init() {
    int i = blockIdx.x * blockDim.x + threadIdx.x;
    if (i < N_NODES) { g_dinv[i] = 1.0f; g_deg[i] = 0; }
}

__device__ __forceinline__ void decode_edge(const int* __restrict__ ei32, int e,
                                            int& r, int& c) {
    if (g_is64) {
        r = ei32[2 * (size_t)e];
        c = ei32[2 * ((size_t)E_EDGES + e)];
    } else {
        r = ei32[e];
        c = ei32[(size_t)E_EDGES + e];
    }
    if ((unsigned)r >= N_NODES) r = 0;
    if ((unsigned)c >= N_NODES) c = 0;
}

__global__ void k_count(const int* __restrict__ ei32, const float* __restrict__ ew) {
    int e = blockIdx.x * blockDim.x + threadIdx.x;
    if (e >= E_EDGES) return;
    int r, c; decode_edge(ei32, e, r, c);
    atomicAdd(&g_deg[c], 1);
    atomicAdd(&g_dinv[c], ew[e]);
}

__global__ void k_rsqrt() {
    int i = blockIdx.x * blockDim.x + threadIdx.x;
    if (i < N_NODES) g_dinv[i] = rsqrtf(g_dinv[i]);
}

// --- prefix scan of g_deg -> exclusive offsets g_off -----------------------
__global__ void k_scan1() {
    __shared__ int sm[SCAN_T];
    int b = blockIdx.x, t = threadIdx.x;
    int base = b * SCAN_E + t * SCAN_V;
    int v[SCAN_V]; int s = 0;
    #pragma unroll
    for (int j = 0; j < SCAN_V; j++) {
        v[j] = (base + j < N_NODES) ? g_deg[base + j] : 0;
        s += v[j];
    }
    sm[t] = s; __syncthreads();
    for (int off = 1; off < SCAN_T; off <<= 1) {
        int x = (t >= off) ? sm[t - off] : 0;
        __syncthreads(); sm[t] += x; __syncthreads();
    }
    if (t == SCAN_T - 1) g_bsum[b] = sm[t];
    int run = (t > 0) ? sm[t - 1] : 0;
    #pragma unroll
    for (int j = 0; j < SCAN_V; j++) {
        if (base + j < N_NODES) g_off[base + j] = run;
        run += v[j];
    }
}
__global__ void k_scan2() {
    __shared__ int sm[128];
    int t = threadIdx.x;
    sm[t] = (t < SCAN_NB) ? g_bsum[t] : 0;
    __syncthreads();
    for (int off = 1; off < 128; off <<= 1) {
        int x = (t >= off) ? sm[t - off] : 0;
        __syncthreads(); sm[t] += x; __syncthreads();
    }
    if (t < SCAN_NB) g_bpre[t] = (t > 0) ? sm[t - 1] : 0;
}
__global__ void k_scan3() {
    int i = blockIdx.x * blockDim.x + threadIdx.x;
    if (i < N_NODES) {
        int o = g_off[i] + g_bpre[i / SCAN_E];
        g_off[i] = o;
        g_cur[i] = o;
    }
    if (i == 0) g_off[N_NODES] = E_EDGES;
}

// place: fold dinv[row] into the stored weight (dinv ready before this)
__global__ void k_place(const int* __restrict__ ei32, const float* __restrict__ ew) {
    int e = blockIdx.x * blockDim.x + threadIdx.x;
    if (e >= E_EDGES) return;
    int r, c; decode_edge(ei32, e, r, c);
    int pos = atomicAdd(&g_cur[c], 1);
    float wf = ew[e] * g_dinv[r];
    g_erec[pos] = make_int2(r, __float_as_int(wf));
}

// ---------------------------------------------------------------------------
// GEMM1: g_hsh = fp16(A @ W1). W1 (64KB) + A tile in smem. No dinv here.
__global__ void __launch_bounds__(256) k_gemm1(const float* __restrict__ A,
                                               const float* __restrict__ W) {
    extern __shared__ float sm[];
    float* Ws = sm;              // 128*128
    float* As = sm + 128 * 128;  // 64*128
    int tid = threadIdx.x;
    int bm  = blockIdx.x * 64;

    const float4* Wv  = (const float4*)W;
    float4*       Wsv = (float4*)Ws;
    #pragma unroll 4
    for (int i = tid; i < 128 * 32; i += 256) Wsv[i] = Wv[i];

    float4* Asv = (float4*)As;
    #pragma unroll 2
    for (int i = tid; i < 64 * 32; i += 256) {
        int r = bm + (i >> 5);
        float4 v = make_float4(0.f, 0.f, 0.f, 0.f);
        if (r < N_NODES) v = ((const float4*)A)[(size_t)r * 32 + (i & 31)];
        Asv[i] = v;
    }
    __syncthreads();

    int tx = tid & 31;
    int ty = tid >> 5;

    float acc[8][4];
    #pragma unroll
    for (int i = 0; i < 8; i++)
        #pragma unroll
        for (int j = 0; j < 4; j++) acc[i][j] = 0.f;

    #pragma unroll 4
    for (int k = 0; k < 128; k++) {
        float4 b = ((const float4*)(Ws + k * 128))[tx];
        #pragma unroll
        for (int i = 0; i < 8; i++) {
            float a = As[(ty * 8 + i) * 128 + k];
            acc[i][0] += a * b.x;
            acc[i][1] += a * b.y;
            acc[i][2] += a * b.z;
            acc[i][3] += a * b.w;
        }
    }

    #pragma unroll
    for (int i = 0; i < 8; i++) {
        int r = bm + ty * 8 + i;
        if (r < N_NODES) {
            __half2 h0 = __floats2half2_rn(acc[i][0], acc[i][1]);
            __half2 h1 = __floats2half2_rn(acc[i][2], acc[i][3]);
            uint2 u;
            u.x = *(unsigned*)&h0;
            u.y = *(unsigned*)&h1;
            ((uint2*)(g_hsh + (size_t)r * 128))[tx] = u;
        }
    }
}

// ---------------------------------------------------------------------------
// Layer-1 aggregation + epilogue: warp per node, fp16 gathers.
__global__ void __launch_bounds__(256) k_agg1(const float* __restrict__ b1) {
    int node = blockIdx.x * 8 + (threadIdx.x >> 5);
    if (node >= N_NODES) return;
    int lane = threadIdx.x & 31;
    const uint2* hsv = (const uint2*)g_hsh;   // 4 halves per uint2, 32 per row

    float di = g_dinv[node];

    uint2 s = hsv[(size_t)node * 32 + lane];  // self term (raw)
    float2 f0 = __half22float2(*(__half2*)&s.x);
    float2 f1 = __half22float2(*(__half2*)&s.y);
    float4 acc = make_float4(f0.x * di, f0.y * di, f1.x * di, f1.y * di);

    int e   = g_off[node];
    int end = g_off[node + 1];

    for (; e + 4 <= end; e += 4) {
        int2 a0 = g_erec[e],     a1 = g_erec[e + 1];
        int2 a2 = g_erec[e + 2], a3 = g_erec[e + 3];
        uint2 v0 = __ldg(hsv + (size_t)a0.x * 32 + lane);
        uint2 v1 = __ldg(hsv + (size_t)a1.x * 32 + lane);
        uint2 v2 = __ldg(hsv + (size_t)a2.x * 32 + lane);
        uint2 v3 = __ldg(hsv + (size_t)a3.x * 32 + lane);
        float w0 = __int_as_float(a0.y), w1 = __int_as_float(a1.y);
        float w2 = __int_as_float(a2.y), w3 = __int_as_float(a3.y);
        float2 p, q;
        p = __half22float2(*(__half2*)&v0.x); q = __half22float2(*(__half2*)&v0.y);
        acc.x += p.x * w0; acc.y += p.y * w0; acc.z += q.x * w0; acc.w += q.y * w0;
        p = __half22float2(*(__half2*)&v1.x); q = __half22float2(*(__half2*)&v1.y);
        acc.x += p.x * w1; acc.y += p.y * w1; acc.z += q.x * w1; acc.w += q.y * w1;
        p = __half22float2(*(__half2*)&v2.x); q = __half22float2(*(__half2*)&v2.y);
        acc.x += p.x * w2; acc.y += p.y * w2; acc.z += q.x * w2; acc.w += q.y * w2;
        p = __half22float2(*(__half2*)&v3.x); q = __half22float2(*(__half2*)&v3.y);
        acc.x += p.x * w3; acc.y += p.y * w3; acc.z += q.x * w3; acc.w += q.y * w3;
    }
    for (; e < end; e++) {
        int2 a = g_erec[e];
        uint2 v = __ldg(hsv + (size_t)a.x * 32 + lane);
        float w = __int_as_float(a.y);
        float2 p = __half22float2(*(__half2*)&v.x);
        float2 q = __half22float2(*(__half2*)&v.y);
        acc.x += p.x * w; acc.y += p.y * w; acc.z += q.x * w; acc.w += q.y * w;
    }

    float4 bb = ((const float4*)b1)[lane];
    float4 o;
    o.x = fmaxf(acc.x * di + bb.x, 0.f);
    o.y = fmaxf(acc.y * di + bb.y, 0.f);
    o.z = fmaxf(acc.z * di + bb.z, 0.f);
    o.w = fmaxf(acc.w * di + bb.w, 0.f);
    ((float4*)g_acc)[(size_t)node * 32 + lane] = o;
}

// ---------------------------------------------------------------------------
// GEMM2: g_h2 = x @ W2 (raw, no dinv), x in g_acc.
__global__ void __launch_bounds__(256) k_gemm2(const float* __restrict__ W2) {
    __shared__ float W2s[128 * 16];
    __shared__ float Xs[64 * 132];
    int tid = threadIdx.x;
    int bm  = blockIdx.x * 64;

    for (int i = tid; i < 128 * 16 / 4; i += 256)
        ((float4*)W2s)[i] = ((const float4*)W2)[i];

    for (int i = tid; i < 64 * 32; i += 256) {
        int r  = i >> 5;
        int c4 = i & 31;
        float4 v = make_float4(0.f, 0.f, 0.f, 0.f);
        int gr = bm + r;
        if (gr < N_NODES) v = ((const float4*)g_acc)[(size_t)gr * 32 + c4];
        *(float4*)&Xs[r * 132 + c4 * 4] = v;
    }
    __syncthreads();

    int nl = tid >> 2;
    int cg = (tid & 3) * 4;
    float a0 = 0.f, a1 = 0.f, a2 = 0.f, a3 = 0.f;
    #pragma unroll 8
    for (int k = 0; k < 128; k++) {
        float  a = Xs[nl * 132 + k];
        float4 b = *(const float4*)&W2s[k * 16 + cg];
        a0 += a * b.x; a1 += a * b.y; a2 += a * b.z; a3 += a * b.w;
    }
    int r = bm + nl;
    if (r < N_NODES) {
        ((float4*)(g_h2 + (size_t)r * 16))[tid & 3] =
            make_float4(a0, a1, a2, a3);
    }
}

// ---------------------------------------------------------------------------
// Layer-2 aggregation + epilogue: half-warp per node (16 lanes = 16 classes).
__global__ void __launch_bounds__(256) k_agg2(const float* __restrict__ b2,
                                              float* __restrict__ out) {
    int node = blockIdx.x * 16 + (threadIdx.x >> 4);
    if (node >= N_NODES) return;
    int l = threadIdx.x & 15;
    const float* h2 = g_h2;

    float di = g_dinv[node];
    float acc = h2[(size_t)node * 16 + l] * di;      // self term

    int e   = g_off[node];
    int end = g_off[node + 1];

    for (; e + 4 <= end; e += 4) {
        int2 a0 = g_erec[e],     a1 = g_erec[e + 1];
        int2 a2 = g_erec[e + 2], a3 = g_erec[e + 3];
        float v0 = __ldg(h2 + (size_t)a0.x * 16 + l);
        float v1 = __ldg(h2 + (size_t)a1.x * 16 + l);
        float v2 = __ldg(h2 + (size_t)a2.x * 16 + l);
        float v3 = __ldg(h2 + (size_t)a3.x * 16 + l);
        acc += v0 * __int_as_float(a0.y);
        acc += v1 * __int_as_float(a1.y);
        acc += v2 * __int_as_float(a2.y);
        acc += v3 * __int_as_float(a3.y);
    }
    for (; e < end; e++) {
        int2 a = g_erec[e];
        acc += __ldg(h2 + (size_t)a.x * 16 + l) * __int_as_float(a.y);
    }

    out[(size_t)node * 16 + l] = di * acc + b2[l];
}

// ---------------------------------------------------------------------------
extern "C" void kernel_launch(void* const* d_in, const int* in_sizes, int n_in,
                              void* d_out, int out_size) {
    const int*   ei32 = (const int*)d_in[0];
    const float* ew   = (const float*)d_in[1];
    const float* emb  = (const float*)d_in[2];
    const float* W1   = (const float*)d_in[3];
    const float* b1   = (const float*)d_in[4];
    const float* W2   = (const float*)d_in[5];
    const float* b2   = (const float*)d_in[6];
    float*       out  = (float*)d_out;

    cudaFuncSetAttribute(k_gemm1, cudaFuncAttributeMaxDynamicSharedMemorySize,
                         (128 * 128 + 64 * 128) * sizeof(float));

    // CSR build + dinv
    k_detect<<<1, 32>>>(ei32);
    k_init<<<(N_NODES + 255) / 256, 256>>>();
    k_count<<<(E_EDGES + 255) / 256, 256>>>(ei32, ew);
    k_rsqrt<<<(N_NODES + 255) / 256, 256>>>();
    k_scan1<<<SCAN_NB, SCAN_T>>>();
    k_scan2<<<1, 128>>>();
    k_scan3<<<(N_NODES + 255) / 256, 256>>>();
    k_place<<<(E_EDGES + 255) / 256, 256>>>(ei32, ew);

    // layer 1
    k_gemm1<<<(N_NODES + 63) / 64, 256,
              (128 * 128 + 64 * 128) * sizeof(float)>>>(emb, W1);
    k_agg1<<<(N_NODES + 7) / 8, 256>>>(b1);

    // layer 2
    k_gemm2<<<(N_NODES + 63) / 64, 256>>>(W2);
    k_agg2<<<(N_NODES + 15) / 16, 256>>>(b2, out);
}